// round 7
// baseline (speedup 1.0000x reference)
#include <cuda_runtime.h>

// 2-layer GRU (PyTorch semantics) + linear head. T=512, B=4096, I=2, H=64.
// 128 persistent blocks x 512 threads = FOUR independent 128-thread groups,
// each owning 8 batch rows end-to-end. Groups share read-only SMEM weights and
// sync only on a group-local 128-wide named barrier (1 per timestep).
// Warp w belongs to group w>>2 and SMSP w%4  ->  every SMSP hosts one warp of
// each group: barrier stalls idle only 1/4 of a scheduler's warps.
// Per-thread tile: 1 j-column x 4 batch rows, FULL k (no k-split, no shfl
// exchange). f32x2 lanes pack (even-k, odd-k) partial sums; one fold at gates.

#define TT   512
#define BB   4096
#define NBLK 128
#define NTHR 512

typedef unsigned long long u64;

// SMEM (floats):
//  w0 [32 kp][384]: per kp: RZ block (64 j x {R u64, Z u64}) + N (64 j x u64)
//  w1 [64 kp][384]: kp<32 = Wih1, kp>=32 = Whh1, same per-kp format
//  h  [4 group][ hp0 2buf x 512 | hp1 2buf x 512 ]  rows: [kp][b_local 0..7][e]
#define OFF_W0 0
#define OFF_W1 12288
#define OFF_H  36864
#define SMEM_FLOATS (OFF_H + 4*2048)
#define SMEM_BYTES  (SMEM_FLOATS * 4)   // 180224

__device__ __forceinline__ void ffma2(u64& d, u64 a, u64 b) {
    asm("fma.rn.f32x2 %0, %1, %2, %0;" : "+l"(d) : "l"(a), "l"(b));
}
__device__ __forceinline__ float fold(u64 v) {
    float lo, hi;
    asm("mov.b64 {%0,%1}, %2;" : "=f"(lo), "=f"(hi) : "l"(v));
    return lo + hi;
}
__device__ __forceinline__ float tanh_(float x) {
    float r; asm("tanh.approx.f32 %0, %1;" : "=f"(r) : "f"(x)); return r;
}
__device__ __forceinline__ float sigm(float x) {
    return fmaf(tanh_(0.5f * x), 0.5f, 0.5f);
}

#define GRPBAR(id) asm volatile("bar.sync %0, 128;" :: "r"(id) : "memory")

// GEMM over NKP k-pairs. wrz = base + j*4, wn = base + 256 + j*2 (stride 384).
// hb = h rows base + bg*8 (stride 16 floats/kp). Accumulates R,Z,N for 4 rows.
template<int NKP>
__device__ __forceinline__ void gemm_rzn(const float* __restrict__ wrz,
                                         const float* __restrict__ wn,
                                         const float* __restrict__ hb,
                                         u64 aR[4], u64 aZ[4], u64 aN[4])
{
    #pragma unroll 4
    for (int kp = 0; kp < NKP; ++kp) {
        ulonglong2 wv = *(const ulonglong2*)(wrz + kp * 384);   // R,Z pair for my j
        u64 wNv = *(const u64*)(wn + kp * 384);
        const float* hr = hb + kp * 16;
        ulonglong2 h01 = *(const ulonglong2*)(hr);
        ulonglong2 h23 = *(const ulonglong2*)(hr + 4);
        u64 hv[4] = { h01.x, h01.y, h23.x, h23.y };
        #pragma unroll
        for (int b = 0; b < 4; ++b) {
            ffma2(aR[b], hv[b], wv.x);
            ffma2(aZ[b], hv[b], wv.y);
            ffma2(aN[b], hv[b], wNv);
        }
    }
}

extern "C" __global__ void __launch_bounds__(NTHR, 1)
gru2_kernel(const float* __restrict__ gx,
            const float* __restrict__ Wih0, const float* __restrict__ Whh0,
            const float* __restrict__ bih0, const float* __restrict__ bhh0,
            const float* __restrict__ Wih1, const float* __restrict__ Whh1,
            const float* __restrict__ bih1, const float* __restrict__ bhh1,
            const float* __restrict__ Wp,   const float* __restrict__ bp,
            float* __restrict__ out)
{
    extern __shared__ __align__(16) float sm[];
    const int tid = threadIdx.x;

    // ---- one-time weight staging ----
    for (int i = tid; i < 12288; i += NTHR) {
        int kp = i / 384, r = i % 384;
        float v;
        if (r < 256) {
            int j = r >> 2, sub = r & 3, gate = sub >> 1, e = sub & 1;
            v = Whh0[(gate * 64 + j) * 64 + 2 * kp + e];
        } else {
            int rr = r - 256, j = rr >> 1, e = rr & 1;
            v = Whh0[(128 + j) * 64 + 2 * kp + e];
        }
        sm[OFF_W0 + i] = v;
    }
    for (int i = tid; i < 24576; i += NTHR) {
        int kp = i / 384, r = i % 384;
        const float* W = (kp < 32) ? Wih1 : Whh1;
        int k0 = 2 * (kp & 31);
        float v;
        if (r < 256) {
            int j = r >> 2, sub = r & 3, gate = sub >> 1, e = sub & 1;
            v = W[(gate * 64 + j) * 64 + k0 + e];
        } else {
            int rr = r - 256, j = rr >> 1, e = rr & 1;
            v = W[(128 + j) * 64 + k0 + e];
        }
        sm[OFF_W1 + i] = v;
    }
    for (int i = tid; i < 4 * 2048; i += NTHR) sm[OFF_H + i] = 0.0f;

    // ---- per-thread mapping ----
    // group = warp>>2  -> group g holds warps {4g..4g+3}; warp%4 = SMSP.
    const int warp   = tid >> 5;
    const int g      = warp >> 2;           // 0..3
    const int warp_g = warp & 3;            // 0..3 within group
    const int lane   = tid & 31;
    const int jq     = lane & 15;
    const int bg     = lane >> 4;           // which 4 of the group's 8 rows
    const int j      = warp_g * 16 + jq;    // my j column (0..63)
    const int kpj    = j >> 1, ej = j & 1;
    const int blf0   = bg * 4;              // first local row (of 8)
    const int bglob  = blockIdx.x * 32 + g * 8 + blf0;
    const int bar_id = g + 1;

    // gate constants
    const float wxr0 = Wih0[j*2],       wxr1 = Wih0[j*2+1];
    const float wxz0 = Wih0[(64+j)*2],  wxz1 = Wih0[(64+j)*2+1];
    const float wxn0 = Wih0[(128+j)*2], wxn1 = Wih0[(128+j)*2+1];
    const float br0 = bih0[j]    + bhh0[j];
    const float bz0 = bih0[64+j] + bhh0[64+j];
    const float bnx0 = bih0[128+j], bnh0 = bhh0[128+j];
    const float br1 = bih1[j]    + bhh1[j];
    const float bz1 = bih1[64+j] + bhh1[64+j];
    const float bnx1 = bih1[128+j], bnh1 = bhh1[128+j];

    // weight pointers (constant over t)
    const float* w0rz = sm + OFF_W0 + j * 4;
    const float* w0n  = sm + OFF_W0 + 256 + j * 2;
    const float* w1rz = sm + OFF_W1 + j * 4;            // kp 0..31: Wih1
    const float* w1n  = sm + OFF_W1 + 256 + j * 2;
    const float* w1rzB = w1rz + 32 * 384;               // kp 32..63: Whh1
    const float* w1nB  = w1n  + 32 * 384;

    // group h arrays: [kp][8 rows][2]
    float* hp0 = sm + OFF_H + g * 2048;     // 2 bufs x 512
    float* hp1 = hp0 + 1024;                // 2 bufs x 512
    const int bgf = bg * 8;                 // float offset of my 4-row slice

    float hprev0[4] = {0.f, 0.f, 0.f, 0.f};
    float hprev1[4] = {0.f, 0.f, 0.f, 0.f};

    __syncthreads();

    for (int t = 0; t < TT; ++t) {
        const int cur = t & 1, nxt = cur ^ 1;
        float* hp0c = hp0 + cur * 512;
        float* hp0n = hp0 + nxt * 512;
        float* hp1c = hp1 + cur * 512;
        float* hp1n = hp1 + nxt * 512;

        // x(t) for my 4 rows (8 consecutive floats)
        const float* xb = gx + ((size_t)t * BB + bglob) * 2;
        float4 xq0 = *(const float4*)(xb);
        float4 xq1 = *(const float4*)(xb + 4);
        float xf[8] = { xq0.x, xq0.y, xq0.z, xq0.w, xq1.x, xq1.y, xq1.z, xq1.w };

        // ======== G0: layer-0 GEMM, full k (32 kp) over hp0[cur] ========
        u64 aR[4], aZ[4], aN[4];
        #pragma unroll
        for (int b = 0; b < 4; ++b) { aR[b] = 0; aZ[b] = 0; aN[b] = 0; }
        gemm_rzn<32>(w0rz, w0n, hp0c + bgf, aR, aZ, aN);

        // ======== E0: gates; write h0(t) -> hp0[nxt] ========
        #pragma unroll
        for (int i = 0; i < 4; ++i) {
            float sR = fold(aR[i]), sZ = fold(aZ[i]), sN = fold(aN[i]);
            float x0 = xf[2*i], x1 = xf[2*i+1];
            float r = sigm(sR + x0 * wxr0 + x1 * wxr1 + br0);
            float z = sigm(sZ + x0 * wxz0 + x1 * wxz1 + bz0);
            float n = tanh_(x0 * wxn0 + x1 * wxn1 + bnx0 + r * (sN + bnh0));
            float h = n + z * (hprev0[i] - n);
            hprev0[i] = h;
            hp0n[kpj * 16 + (blf0 + i) * 2 + ej] = h;
        }
        GRPBAR(bar_id);   // h0(t) visible within group (only bar this step)

        // ======== G1: layer-1 GEMM: input side over h0(t), recurrent over h1(t-1)
        u64 cR[4], cZ[4], cNx[4], cNh[4];
        #pragma unroll
        for (int b = 0; b < 4; ++b) { cR[b] = 0; cZ[b] = 0; cNx[b] = 0; cNh[b] = 0; }
        gemm_rzn<32>(w1rz,  w1n,  hp0n + bgf, cR, cZ, cNx);
        gemm_rzn<32>(w1rzB, w1nB, hp1c + bgf, cR, cZ, cNh);

        // ======== E1: gates; write h1(t) -> hp1[nxt] ========
        #pragma unroll
        for (int i = 0; i < 4; ++i) {
            float sR = fold(cR[i]), sZ = fold(cZ[i]);
            float nx = fold(cNx[i]), nh = fold(cNh[i]);
            float r = sigm(sR + br1);
            float z = sigm(sZ + bz1);
            float n = tanh_(nx + bnx1 + r * (nh + bnh1));
            float h = n + z * (hprev1[i] - n);
            hprev1[i] = h;
            hp1n[kpj * 16 + (blf0 + i) * 2 + ej] = h;
        }
        // no second barrier: next step's bar (after E0) orders E1 stores before
        // G1(t+1) reads hp1; G0(t+1) touches only hp0 (written pre-bar in E0).
    }

    // ---- projection: out[b] = sum_j Wp[j]*h0f[j] + Wp[64+j]*h1f[j] + bp ----
    __syncthreads();   // all groups done with h buffers
    {
        float* scr = sm + OFF_H;   // reuse h area: [32 b][stride 68]
        const float wp0 = Wp[j], wp1 = Wp[64 + j];
        #pragma unroll
        for (int i = 0; i < 4; ++i)
            scr[(g * 8 + blf0 + i) * 68 + j] = wp0 * hprev0[i] + wp1 * hprev1[i];
        __syncthreads();
        if (tid < 32) {
            float s = bp[0];
            #pragma unroll 8
            for (int jj = 0; jj < 64; ++jj) s += scr[tid * 68 + jj];
            out[blockIdx.x * 32 + tid] = s;
        }
    }
}

extern "C" void kernel_launch(void* const* d_in, const int* in_sizes, int n_in,
                              void* d_out, int out_size)
{
    (void)in_sizes; (void)n_in; (void)out_size;
    const float* x    = (const float*)d_in[0];
    const float* Wih0 = (const float*)d_in[1];
    const float* Whh0 = (const float*)d_in[2];
    const float* bih0 = (const float*)d_in[3];
    const float* bhh0 = (const float*)d_in[4];
    const float* Wih1 = (const float*)d_in[5];
    const float* Whh1 = (const float*)d_in[6];
    const float* bih1 = (const float*)d_in[7];
    const float* bhh1 = (const float*)d_in[8];
    const float* Wp   = (const float*)d_in[9];
    const float* bp   = (const float*)d_in[10];
    float* out = (float*)d_out;

    cudaFuncSetAttribute(gru2_kernel, cudaFuncAttributeMaxDynamicSharedMemorySize, SMEM_BYTES);
    gru2_kernel<<<NBLK, NTHR, SMEM_BYTES>>>(x, Wih0, Whh0, bih0, bhh0,
                                            Wih1, Whh1, bih1, bhh1, Wp, bp, out);
}

// round 8
// speedup vs baseline: 1.0649x; 1.0649x over previous
#include <cuda_runtime.h>

// 2-layer GRU (PyTorch semantics) + linear head. T=512, B=4096, I=2, H=64.
// 128 persistent blocks x 512 threads = FOUR independent 128-thread groups,
// each owning 8 batch rows end-to-end. group = warp>>2, so SMSP s hosts warps
// {s, s+4, s+8, s+12} = one warp of EACH group: a group-barrier stall idles
// only 1/4 of each scheduler's warps; groups drift and cover each other's
// latency phases.
// Per-thread tile (same arithmetic shape as the best R6 kernel): 1 j-column x
// 8 batch rows in the GEMM, k-split 2-ways in-warp (lane bit 4), f32x2 lanes
// pack (even-k, odd-k) partials; k-split reduced via shfl.bfly(16); each
// thread finalizes 4 rows. 1 group-barrier per timestep.

#define TT   512
#define BB   4096
#define NBLK 128
#define NTHR 512

typedef unsigned long long u64;

// SMEM (floats):
//  w0 [32 kp][384]: per kp: RZ block (64 j x {R u64, Z u64}) + N (64 j x u64)
//  w1 [64 kp][384]: kp<32 = Wih1, kp>=32 = Whh1, same per-kp format
//  h per group (stride 2068):
//    hp0: 2 bufs x 516:  [kp0..15 at 0][pad 4][kp16..31 at 260]   (h0)
//    hp1: at +1036, 2 bufs x 516: [kp0..31 at 0..511][pad]        (h1)
//  pads chosen so concurrent ks0/ks1 h streams hit disjoint bank windows.
#define OFF_W0 0
#define OFF_W1 12288
#define OFF_H  36864
#define GRPH   2068
#define SMEM_FLOATS (OFF_H + 4*GRPH)
#define SMEM_BYTES  (SMEM_FLOATS * 4)

__device__ __forceinline__ void ffma2(u64& d, u64 a, u64 b) {
    asm("fma.rn.f32x2 %0, %1, %2, %0;" : "+l"(d) : "l"(a), "l"(b));
}
__device__ __forceinline__ void fadd2(u64& d, u64 a) {
    asm("add.rn.f32x2 %0, %0, %1;" : "+l"(d) : "l"(a));
}
__device__ __forceinline__ float fold(u64 v) {
    float lo, hi;
    asm("mov.b64 {%0,%1}, %2;" : "=f"(lo), "=f"(hi) : "l"(v));
    return lo + hi;
}
__device__ __forceinline__ float tanh_(float x) {
    float r; asm("tanh.approx.f32 %0, %1;" : "=f"(r) : "f"(x)); return r;
}
__device__ __forceinline__ float sigm(float x) {
    return fmaf(tanh_(0.5f * x), 0.5f, 0.5f);
}

#define GRPBAR(id) asm volatile("bar.sync %0, 128;" :: "r"(id) : "memory")

// GEMM over NKP k-pairs. wrz = w base + j*4 (stride 384), wn = +256 + j*2.
// hb = h rows base (16 floats per kp, whole group row = 8 b x 2 e).
template<int NKP>
__device__ __forceinline__ void gemm_rzn(const float* __restrict__ wrz,
                                         const float* __restrict__ wn,
                                         const float* __restrict__ hb,
                                         u64 aR[8], u64 aZ[8], u64 aN[8])
{
    #pragma unroll 4
    for (int kp = 0; kp < NKP; ++kp) {
        ulonglong2 wv = *(const ulonglong2*)(wrz + kp * 384);   // R,Z for my j
        u64 wNv = *(const u64*)(wn + kp * 384);
        const float* hr = hb + kp * 16;
        ulonglong2 h01 = *(const ulonglong2*)(hr);
        ulonglong2 h23 = *(const ulonglong2*)(hr + 4);
        ulonglong2 h45 = *(const ulonglong2*)(hr + 8);
        ulonglong2 h67 = *(const ulonglong2*)(hr + 12);
        u64 hv[8] = { h01.x, h01.y, h23.x, h23.y, h45.x, h45.y, h67.x, h67.y };
        #pragma unroll
        for (int b = 0; b < 8; ++b) {
            ffma2(aR[b], hv[b], wv.x);
            ffma2(aZ[b], hv[b], wv.y);
            ffma2(aN[b], hv[b], wNv);
        }
    }
}

extern "C" __global__ void __launch_bounds__(NTHR, 1)
gru2_kernel(const float* __restrict__ gx,
            const float* __restrict__ Wih0, const float* __restrict__ Whh0,
            const float* __restrict__ bih0, const float* __restrict__ bhh0,
            const float* __restrict__ Wih1, const float* __restrict__ Whh1,
            const float* __restrict__ bih1, const float* __restrict__ bhh1,
            const float* __restrict__ Wp,   const float* __restrict__ bp,
            float* __restrict__ out)
{
    extern __shared__ __align__(16) float sm[];
    const int tid = threadIdx.x;

    // ---- one-time weight staging ----
    for (int i = tid; i < 12288; i += NTHR) {
        int kp = i / 384, r = i % 384;
        float v;
        if (r < 256) {
            int j = r >> 2, sub = r & 3, gate = sub >> 1, e = sub & 1;
            v = Whh0[(gate * 64 + j) * 64 + 2 * kp + e];
        } else {
            int rr = r - 256, j = rr >> 1, e = rr & 1;
            v = Whh0[(128 + j) * 64 + 2 * kp + e];
        }
        sm[OFF_W0 + i] = v;
    }
    for (int i = tid; i < 24576; i += NTHR) {
        int kp = i / 384, r = i % 384;
        const float* W = (kp < 32) ? Wih1 : Whh1;
        int k0 = 2 * (kp & 31);
        float v;
        if (r < 256) {
            int j = r >> 2, sub = r & 3, gate = sub >> 1, e = sub & 1;
            v = W[(gate * 64 + j) * 64 + k0 + e];
        } else {
            int rr = r - 256, j = rr >> 1, e = rr & 1;
            v = W[(128 + j) * 64 + k0 + e];
        }
        sm[OFF_W1 + i] = v;
    }
    for (int i = tid; i < 4 * GRPH; i += NTHR) sm[OFF_H + i] = 0.0f;

    // ---- per-thread mapping ----
    const int warp   = tid >> 5;
    const int g      = warp >> 2;           // group 0..3 ; SMSP = warp & 3
    const int warp_g = warp & 3;            // warp within group
    const int lane   = tid & 31;
    const int ks     = lane >> 4;           // k-split half
    const int jq     = lane & 15;
    const int j      = warp_g * 16 + jq;    // my j column (0..63)
    const int kpj    = j >> 1, ej = j & 1;
    const int blf0   = ks * 4;              // first finalized local row (of 8)
    const int bglob  = blockIdx.x * 32 + g * 8 + blf0;
    const int bar_id = g + 1;

    // gate constants
    const float wxr0 = Wih0[j*2],       wxr1 = Wih0[j*2+1];
    const float wxz0 = Wih0[(64+j)*2],  wxz1 = Wih0[(64+j)*2+1];
    const float wxn0 = Wih0[(128+j)*2], wxn1 = Wih0[(128+j)*2+1];
    const float br0 = bih0[j]    + bhh0[j];
    const float bz0 = bih0[64+j] + bhh0[64+j];
    const float bnx0 = bih0[128+j], bnh0 = bhh0[128+j];
    const float br1 = bih1[j]    + bhh1[j];
    const float bz1 = bih1[64+j] + bhh1[64+j];
    const float bnx1 = bih1[128+j], bnh1 = bhh1[128+j];

    // weight pointers (constant over t)
    const float* w0rz = sm + OFF_W0 + (ks * 16) * 384 + j * 4;  // my k-half
    const float* w0n  = sm + OFF_W0 + (ks * 16) * 384 + 256 + j * 2;
    const float* w1rz = sm + OFF_W1 + (ks * 32) * 384 + j * 4;  // ks0: Wih1, ks1: Whh1
    const float* w1n  = sm + OFF_W1 + (ks * 32) * 384 + 256 + j * 2;

    // group h arrays
    float* hg  = sm + OFF_H + g * GRPH;
    float* hp0 = hg;            // 2 bufs x 516 (split layout, pad at 256)
    float* hp1 = hg + 1036;     // 2 bufs x 516 (plain 32 kp x 16)

    // store offsets (within a buffer)
    const int st0_off = ((kpj < 16) ? kpj * 16 : 260 + (kpj - 16) * 16) + blf0 * 2 + ej;
    const int st1_off = kpj * 16 + blf0 * 2 + ej;

    float hprev0[4] = {0.f, 0.f, 0.f, 0.f};
    float hprev1[4] = {0.f, 0.f, 0.f, 0.f};

    __syncthreads();

    for (int t = 0; t < TT; ++t) {
        const int cur = t & 1, nxt = cur ^ 1;
        float* hp0c = hp0 + cur * 516;
        float* hp0n = hp0 + nxt * 516;
        float* hp1c = hp1 + cur * 516;
        float* hp1n = hp1 + nxt * 516;

        // x(t) for my 4 finalized rows
        const float* xb = gx + ((size_t)t * BB + bglob) * 2;
        float4 xq0 = *(const float4*)(xb);
        float4 xq1 = *(const float4*)(xb + 4);
        float xf[8] = { xq0.x, xq0.y, xq0.z, xq0.w, xq1.x, xq1.y, xq1.z, xq1.w };

        // ======== G0: layer-0 GEMM, my k-half (16 kp) over hp0[cur] ========
        u64 aR[8], aZ[8], aN[8];
        #pragma unroll
        for (int b = 0; b < 8; ++b) { aR[b] = 0; aZ[b] = 0; aN[b] = 0; }
        gemm_rzn<16>(w0rz, w0n, hp0c + ks * 260, aR, aZ, aN);

        // ======== E0: k-split reduce + gates; write h0(t) -> hp0[nxt] ========
        #pragma unroll
        for (int i = 0; i < 4; ++i) {
            u64 keepR = ks ? aR[4+i] : aR[i], sndR = ks ? aR[i] : aR[4+i];
            u64 keepZ = ks ? aZ[4+i] : aZ[i], sndZ = ks ? aZ[i] : aZ[4+i];
            u64 keepN = ks ? aN[4+i] : aN[i], sndN = ks ? aN[i] : aN[4+i];
            fadd2(keepR, __shfl_xor_sync(0xffffffffu, sndR, 16));
            fadd2(keepZ, __shfl_xor_sync(0xffffffffu, sndZ, 16));
            fadd2(keepN, __shfl_xor_sync(0xffffffffu, sndN, 16));
            float sR = fold(keepR), sZ = fold(keepZ), sN = fold(keepN);
            float x0 = xf[2*i], x1 = xf[2*i+1];
            float r = sigm(sR + x0 * wxr0 + x1 * wxr1 + br0);
            float z = sigm(sZ + x0 * wxz0 + x1 * wxz1 + bz0);
            float n = tanh_(x0 * wxn0 + x1 * wxn1 + bnx0 + r * (sN + bnh0));
            float h = n + z * (hprev0[i] - n);
            hprev0[i] = h;
            hp0n[st0_off + i * 2] = h;
        }
        GRPBAR(bar_id);   // h0(t) visible within group (only bar this step)

        // ==== G1: layer-1 GEMM. ks0: input side (Wih1) over hp0[nxt] (fresh h0);
        //          ks1: recurrent (Whh1) over hp1[cur]. 32 kp each, split 16+16
        //          so ks0 can skip hp0's mid-pad. ====
        u64 cR[8], cZ[8], cN[8];
        #pragma unroll
        for (int b = 0; b < 8; ++b) { cR[b] = 0; cZ[b] = 0; cN[b] = 0; }
        {
            const float* hbA = ks ? hp1c         : hp0n;
            const float* hbB = ks ? (hp1c + 256) : (hp0n + 260);
            gemm_rzn<16>(w1rz,            w1n,            hbA, cR, cZ, cN);
            gemm_rzn<16>(w1rz + 16 * 384, w1n + 16 * 384, hbB, cR, cZ, cN);
        }

        // ======== E1: exchange + gates; write h1(t) -> hp1[nxt] ========
        #pragma unroll
        for (int i = 0; i < 4; ++i) {
            u64 keepR = ks ? cR[4+i] : cR[i], sndR = ks ? cR[i] : cR[4+i];
            u64 keepZ = ks ? cZ[4+i] : cZ[i], sndZ = ks ? cZ[i] : cZ[4+i];
            u64 keepN = ks ? cN[4+i] : cN[i], sndN = ks ? cN[i] : cN[4+i];
            fadd2(keepR, __shfl_xor_sync(0xffffffffu, sndR, 16));
            fadd2(keepZ, __shfl_xor_sync(0xffffffffu, sndZ, 16));
            u64 rcvN = __shfl_xor_sync(0xffffffffu, sndN, 16);
            float sR = fold(keepR), sZ = fold(keepZ);
            float fm = fold(keepN), fr = fold(rcvN);
            float nx = ks ? fr : fm;      // input-side partial came from ks0
            float nh = ks ? fm : fr;      // recurrent partial came from ks1
            float r = sigm(sR + br1);
            float z = sigm(sZ + bz1);
            float n = tanh_(nx + bnx1 + r * (nh + bnh1));
            float h = n + z * (hprev1[i] - n);
            hprev1[i] = h;
            hp1n[st1_off + i * 2] = h;
        }
        // no second barrier: next step's bar (after E0) orders E1 stores before
        // G1(t+1) reads hp1; the 2-buffer reuse at t+2 is also bar-ordered.
    }

    // ---- projection: out[b] = sum_j Wp[j]*h0f[j] + Wp[64+j]*h1f[j] + bp ----
    __syncthreads();   // all groups done with h buffers
    {
        float* scr = sm + OFF_H;   // [32 b][stride 68]
        const float wp0 = Wp[j], wp1 = Wp[64 + j];
        #pragma unroll
        for (int i = 0; i < 4; ++i)
            scr[(g * 8 + blf0 + i) * 68 + j] = wp0 * hprev0[i] + wp1 * hprev1[i];
        __syncthreads();
        if (tid < 32) {
            float s = bp[0];
            #pragma unroll 8
            for (int jj = 0; jj < 64; ++jj) s += scr[tid * 68 + jj];
            out[blockIdx.x * 32 + tid] = s;
        }
    }
}

extern "C" void kernel_launch(void* const* d_in, const int* in_sizes, int n_in,
                              void* d_out, int out_size)
{
    (void)in_sizes; (void)n_in; (void)out_size;
    const float* x    = (const float*)d_in[0];
    const float* Wih0 = (const float*)d_in[1];
    const float* Whh0 = (const float*)d_in[2];
    const float* bih0 = (const float*)d_in[3];
    const float* bhh0 = (const float*)d_in[4];
    const float* Wih1 = (const float*)d_in[5];
    const float* Whh1 = (const float*)d_in[6];
    const float* bih1 = (const float*)d_in[7];
    const float* bhh1 = (const float*)d_in[8];
    const float* Wp   = (const float*)d_in[9];
    const float* bp   = (const float*)d_in[10];
    float* out = (float*)d_out;

    cudaFuncSetAttribute(gru2_kernel, cudaFuncAttributeMaxDynamicSharedMemorySize, SMEM_BYTES);
    gru2_kernel<<<NBLK, NTHR, SMEM_BYTES>>>(x, Wih0, Whh0, bih0, bhh0,
                                            Wih1, Whh1, bih1, bhh1, Wp, bp, out);
}